// round 11
// baseline (speedup 1.0000x reference)
#include <cuda_runtime.h>
#include <cuda_fp16.h>
#include <stdint.h>

// Problem constants (reference): N=50000, IN_CH=256, OUT_CH=128, NNZ=800000
#define OUT_CH    128
#define OUT_CH4   32          // 16B units per fp32 row == 8B units per fp16 row
#define MAX_N     50000
#define ELL_W     64          // padded entries per row (Poisson(16) tail-safe)

// ---------------- device scratch (no allocations allowed) ----------------
__device__ uint2 g_filtered_h[MAX_N * OUT_CH4];   // [N,128] fp16
__device__ uint2 g_tmp_h[MAX_N * OUT_CH4];        // [N,128] fp16
__device__ int   g_cnt[3][MAX_N];                 // per-row entry counts
__device__ int2  g_ell[3][MAX_N * ELL_W];         // padded (col, val-bits)

// ---------------- fused ELL build: one atomic pass, no hist/scan ---------
__global__ void build_ell_kernel(const int* __restrict__ i0, const float* __restrict__ v0, int n0,
                                 const int* __restrict__ i1, const float* __restrict__ v1, int n1,
                                 const int* __restrict__ i2, const float* __restrict__ v2, int n2,
                                 const float* __restrict__ theta,
                                 int* __restrict__ c0, int* __restrict__ c1,
                                 int* __restrict__ c2,
                                 int2* __restrict__ e0, int2* __restrict__ e1,
                                 int2* __restrict__ e2) {
    int i = blockIdx.x * blockDim.x + threadIdx.x;
    if (i < n0) {
        int r = __ldg(&i0[i]); int c = __ldg(&i0[i + n0]);
        float v = __ldg(&v0[i]);
        int pos = atomicAdd(&c0[r], 1);
        if (pos < ELL_W) e0[r * ELL_W + pos] = make_int2(c, __float_as_int(v));
    }
    if (i < n1) {
        int r = __ldg(&i1[i]); int c = __ldg(&i1[i + n1]);
        float v = __ldg(&v1[i]);
        int pos = atomicAdd(&c1[r], 1);
        if (pos < ELL_W) e1[r * ELL_W + pos] = make_int2(c, __float_as_int(v));
    }
    if (i < n2) {
        int r = __ldg(&i2[i]); int c = __ldg(&i2[i + n2]);
        float v = __ldg(&v2[i]) * __ldg(&theta[c]);   // fold theta into phi
        int pos = atomicAdd(&c2[r], 1);
        if (pos < ELL_W) e2[r * ELL_W + pos] = make_int2(c, __float_as_int(v));
    }
}

// ---------------- gather-based ELL SpMM ----------------
// One warp per output row; lane owns 4 consecutive columns.
// GH: dense rows stored fp16 (uint2/lane) vs fp32 (float4/lane).
// SH: store output fp16 vs fp32. Accumulation always fp32.
// __launch_bounds__(256, 4): allow ~64 regs so the unroll-8 gather batch
// stays live (real MLP), while keeping 32 warps/SM.
template <bool GH, bool SH, bool RELU>
__global__ void __launch_bounds__(256, 4)
spmm_ell_kernel(const int* __restrict__ cnt,
                const int2* __restrict__ ell,
                const void* __restrict__ dense,
                void* __restrict__ out,
                int n) {
    int row = blockIdx.x * (blockDim.x >> 5) + (threadIdx.x >> 5);
    if (row >= n) return;
    int lane = threadIdx.x & 31;

    int e = __ldg(&cnt[row]);
    if (e > ELL_W) e = ELL_W;
    const int2* __restrict__ pairs = ell + (size_t)row * ELL_W;
    const int4* __restrict__ pairs4 = reinterpret_cast<const int4*>(pairs);

    const float4* __restrict__ d4 = reinterpret_cast<const float4*>(dense);
    const uint2*  __restrict__ d2 = reinterpret_cast<const uint2*>(dense);

    float4 acc = make_float4(0.f, 0.f, 0.f, 0.f);

    int i = 0;
    for (; i + 8 <= e; i += 8) {
        // 4 x LDG.128: 8 (col,val) entries
        int4 q0 = __ldg(&pairs4[(i >> 1) + 0]);
        int4 q1 = __ldg(&pairs4[(i >> 1) + 1]);
        int4 q2 = __ldg(&pairs4[(i >> 1) + 2]);
        int4 q3 = __ldg(&pairs4[(i >> 1) + 3]);

        // 8 independent gathers — keep all in flight.
        float4 x0, x1, x2, x3, x4, x5, x6, x7;
        if (GH) {
            uint2 u0 = __ldg(&d2[(size_t)q0.x * OUT_CH4 + lane]);
            uint2 u1 = __ldg(&d2[(size_t)q0.z * OUT_CH4 + lane]);
            uint2 u2 = __ldg(&d2[(size_t)q1.x * OUT_CH4 + lane]);
            uint2 u3 = __ldg(&d2[(size_t)q1.z * OUT_CH4 + lane]);
            uint2 u4 = __ldg(&d2[(size_t)q2.x * OUT_CH4 + lane]);
            uint2 u5 = __ldg(&d2[(size_t)q2.z * OUT_CH4 + lane]);
            uint2 u6 = __ldg(&d2[(size_t)q3.x * OUT_CH4 + lane]);
            uint2 u7 = __ldg(&d2[(size_t)q3.z * OUT_CH4 + lane]);
            float2 a, b;
            a = __half22float2(*reinterpret_cast<__half2*>(&u0.x));
            b = __half22float2(*reinterpret_cast<__half2*>(&u0.y));
            x0 = make_float4(a.x, a.y, b.x, b.y);
            a = __half22float2(*reinterpret_cast<__half2*>(&u1.x));
            b = __half22float2(*reinterpret_cast<__half2*>(&u1.y));
            x1 = make_float4(a.x, a.y, b.x, b.y);
            a = __half22float2(*reinterpret_cast<__half2*>(&u2.x));
            b = __half22float2(*reinterpret_cast<__half2*>(&u2.y));
            x2 = make_float4(a.x, a.y, b.x, b.y);
            a = __half22float2(*reinterpret_cast<__half2*>(&u3.x));
            b = __half22float2(*reinterpret_cast<__half2*>(&u3.y));
            x3 = make_float4(a.x, a.y, b.x, b.y);
            a = __half22float2(*reinterpret_cast<__half2*>(&u4.x));
            b = __half22float2(*reinterpret_cast<__half2*>(&u4.y));
            x4 = make_float4(a.x, a.y, b.x, b.y);
            a = __half22float2(*reinterpret_cast<__half2*>(&u5.x));
            b = __half22float2(*reinterpret_cast<__half2*>(&u5.y));
            x5 = make_float4(a.x, a.y, b.x, b.y);
            a = __half22float2(*reinterpret_cast<__half2*>(&u6.x));
            b = __half22float2(*reinterpret_cast<__half2*>(&u6.y));
            x6 = make_float4(a.x, a.y, b.x, b.y);
            a = __half22float2(*reinterpret_cast<__half2*>(&u7.x));
            b = __half22float2(*reinterpret_cast<__half2*>(&u7.y));
            x7 = make_float4(a.x, a.y, b.x, b.y);
        } else {
            x0 = __ldg(&d4[(size_t)q0.x * OUT_CH4 + lane]);
            x1 = __ldg(&d4[(size_t)q0.z * OUT_CH4 + lane]);
            x2 = __ldg(&d4[(size_t)q1.x * OUT_CH4 + lane]);
            x3 = __ldg(&d4[(size_t)q1.z * OUT_CH4 + lane]);
            x4 = __ldg(&d4[(size_t)q2.x * OUT_CH4 + lane]);
            x5 = __ldg(&d4[(size_t)q2.z * OUT_CH4 + lane]);
            x6 = __ldg(&d4[(size_t)q3.x * OUT_CH4 + lane]);
            x7 = __ldg(&d4[(size_t)q3.z * OUT_CH4 + lane]);
        }

        float v0 = __int_as_float(q0.y), v1 = __int_as_float(q0.w);
        float v2 = __int_as_float(q1.y), v3 = __int_as_float(q1.w);
        float v4 = __int_as_float(q2.y), v5 = __int_as_float(q2.w);
        float v6 = __int_as_float(q3.y), v7 = __int_as_float(q3.w);

        acc.x += v0 * x0.x; acc.y += v0 * x0.y; acc.z += v0 * x0.z; acc.w += v0 * x0.w;
        acc.x += v1 * x1.x; acc.y += v1 * x1.y; acc.z += v1 * x1.z; acc.w += v1 * x1.w;
        acc.x += v2 * x2.x; acc.y += v2 * x2.y; acc.z += v2 * x2.z; acc.w += v2 * x2.w;
        acc.x += v3 * x3.x; acc.y += v3 * x3.y; acc.z += v3 * x3.z; acc.w += v3 * x3.w;
        acc.x += v4 * x4.x; acc.y += v4 * x4.y; acc.z += v4 * x4.z; acc.w += v4 * x4.w;
        acc.x += v5 * x5.x; acc.y += v5 * x5.y; acc.z += v5 * x5.z; acc.w += v5 * x5.w;
        acc.x += v6 * x6.x; acc.y += v6 * x6.y; acc.z += v6 * x6.z; acc.w += v6 * x6.w;
        acc.x += v7 * x7.x; acc.y += v7 * x7.y; acc.z += v7 * x7.z; acc.w += v7 * x7.w;
    }
    for (; i < e; i++) {
        int2 p = __ldg(&pairs[i]);
        float v = __int_as_float(p.y);
        size_t off = (size_t)p.x * OUT_CH4 + lane;
        float4 x;
        if (GH) {
            uint2 u = __ldg(&d2[off]);
            float2 f0 = __half22float2(*reinterpret_cast<__half2*>(&u.x));
            float2 f1 = __half22float2(*reinterpret_cast<__half2*>(&u.y));
            x = make_float4(f0.x, f0.y, f1.x, f1.y);
        } else {
            x = __ldg(&d4[off]);
        }
        acc.x += v * x.x; acc.y += v * x.y; acc.z += v * x.z; acc.w += v * x.w;
    }

    if (RELU) {
        acc.x = acc.x > 0.f ? acc.x : 0.f;
        acc.y = acc.y > 0.f ? acc.y : 0.f;
        acc.z = acc.z > 0.f ? acc.z : 0.f;
        acc.w = acc.w > 0.f ? acc.w : 0.f;
    }

    if (SH) {
        __half2 h0 = __floats2half2_rn(acc.x, acc.y);
        __half2 h1 = __floats2half2_rn(acc.z, acc.w);
        uint2 o;
        o.x = *reinterpret_cast<unsigned*>(&h0);
        o.y = *reinterpret_cast<unsigned*>(&h1);
        reinterpret_cast<uint2*>(out)[(size_t)row * OUT_CH4 + lane] = o;
    } else {
        reinterpret_cast<float4*>(out)[(size_t)row * OUT_CH4 + lane] = acc;
    }
}

// ---------------- host-side orchestration ----------------
extern "C" void kernel_launch(void* const* d_in, const int* in_sizes, int n_in,
                              void* d_out, int out_size) {
    // Inputs: phi_indices, phi_values, phi_inverse_indices, phi_inverse_values,
    // feature_indices, feature_values, weight_matrix, diagonal_weight_filter, dropout
    const int*   phi_idx   = (const int*)d_in[0];
    const float* phi_vals  = (const float*)d_in[1];
    const int*   phii_idx  = (const int*)d_in[2];
    const float* phii_vals = (const float*)d_in[3];
    const int*   feat_idx  = (const int*)d_in[4];
    const float* feat_vals = (const float*)d_in[5];
    const float* weight    = (const float*)d_in[6];
    const float* theta     = (const float*)d_in[7];

    int nnz_phi  = in_sizes[1];
    int nnz_phii = in_sizes[3];
    int nnz_feat = in_sizes[5];
    int n_nodes  = in_sizes[7];
    (void)n_in; (void)out_size;

    float* out = (float*)d_out;
    uint2 *filtered_h, *tmp_h;
    int (*cnt)[MAX_N];
    int2 (*ell)[MAX_N * ELL_W];
    cudaGetSymbolAddress((void**)&filtered_h, g_filtered_h);
    cudaGetSymbolAddress((void**)&tmp_h, g_tmp_h);
    cudaGetSymbolAddress((void**)&cnt, g_cnt);
    cudaGetSymbolAddress((void**)&ell, g_ell);

    const int T = 256;

    // 1) Zero the three count arrays.
    cudaMemsetAsync(cnt, 0, sizeof(int) * 3 * MAX_N);

    // 2) Fused single-pass ELL build for all three matrices.
    int nnz_max = nnz_feat;
    if (nnz_phii > nnz_max) nnz_max = nnz_phii;
    if (nnz_phi  > nnz_max) nnz_max = nnz_phi;
    {
        int blocks = (nnz_max + T - 1) / T;
        build_ell_kernel<<<blocks, T>>>(feat_idx, feat_vals, nnz_feat,
                                        phii_idx, phii_vals, nnz_phii,
                                        phi_idx, phi_vals, nnz_phi,
                                        theta,
                                        cnt[0], cnt[1], cnt[2],
                                        ell[0], ell[1], ell[2]);
    }

    const int WPB = T / 32;
    int spmm_blocks = (n_nodes + WPB - 1) / WPB;

    // 3) filtered(fp16) = feature @ W(fp32)
    spmm_ell_kernel<false, true, false><<<spmm_blocks, T>>>(
        cnt[0], ell[0], weight, filtered_h, n_nodes);
    // 4) tmp(fp16) = phi_inv @ filtered(fp16)
    spmm_ell_kernel<true, true, false><<<spmm_blocks, T>>>(
        cnt[1], ell[1], filtered_h, tmp_h, n_nodes);
    // 5) out(fp32) = relu( (phi*diag(theta)) @ tmp(fp16) )
    spmm_ell_kernel<true, false, true><<<spmm_blocks, T>>>(
        cnt[2], ell[2], tmp_h, out, n_nodes);
}

// round 12
// speedup vs baseline: 1.1489x; 1.1489x over previous
#include <cuda_runtime.h>
#include <cuda_fp16.h>
#include <stdint.h>

// Problem constants (reference): N=50000, IN_CH=256, OUT_CH=128, NNZ=800000
#define OUT_CH    128
#define OUT_CH4   32          // 16B units per fp32 row == 8B units per fp16 row
#define OUT_CHU4  16          // uint4 (8 fp16) units per fp16 row
#define MAX_N     50000
#define ELL_W     64          // padded entries per row (Poisson(16) tail-safe)

// ---------------- device scratch (no allocations allowed) ----------------
__device__ uint2 g_filtered_h[MAX_N * OUT_CH4];   // [N,128] fp16
__device__ uint2 g_tmp_h[MAX_N * OUT_CH4];        // [N,128] fp16
__device__ int   g_cnt[3][MAX_N];                 // per-row entry counts
__device__ int2  g_ell[3][MAX_N * ELL_W];         // padded (col, val-bits)

// ---------------- fused ELL build: one atomic pass (as R10) --------------
__global__ void build_ell_kernel(const int* __restrict__ i0, const float* __restrict__ v0, int n0,
                                 const int* __restrict__ i1, const float* __restrict__ v1, int n1,
                                 const int* __restrict__ i2, const float* __restrict__ v2, int n2,
                                 const float* __restrict__ theta,
                                 int* __restrict__ c0, int* __restrict__ c1,
                                 int* __restrict__ c2,
                                 int2* __restrict__ e0, int2* __restrict__ e1,
                                 int2* __restrict__ e2) {
    int i = blockIdx.x * blockDim.x + threadIdx.x;
    if (i < n0) {
        int r = __ldg(&i0[i]); int c = __ldg(&i0[i + n0]);
        float v = __ldg(&v0[i]);
        int pos = atomicAdd(&c0[r], 1);
        if (pos < ELL_W) e0[r * ELL_W + pos] = make_int2(c, __float_as_int(v));
    }
    if (i < n1) {
        int r = __ldg(&i1[i]); int c = __ldg(&i1[i + n1]);
        float v = __ldg(&v1[i]);
        int pos = atomicAdd(&c1[r], 1);
        if (pos < ELL_W) e1[r * ELL_W + pos] = make_int2(c, __float_as_int(v));
    }
    if (i < n2) {
        int r = __ldg(&i2[i]); int c = __ldg(&i2[i + n2]);
        float v = __ldg(&v2[i]) * __ldg(&theta[c]);   // fold theta into phi
        int pos = atomicAdd(&c2[r], 1);
        if (pos < ELL_W) e2[r * ELL_W + pos] = make_int2(c, __float_as_int(v));
    }
}

// ---------------- feature SpMM (R10 kernel, GH=false path) ---------------
// One warp per row; lane owns 4 fp32 columns; gathers W rows; stores fp16.
__global__ void __launch_bounds__(256)
spmm_ell_f32_kernel(const int* __restrict__ cnt,
                    const int2* __restrict__ ell,
                    const float* __restrict__ dense,   // W [256,128] fp32
                    uint2* __restrict__ out,           // fp16
                    int n) {
    int row = blockIdx.x * (blockDim.x >> 5) + (threadIdx.x >> 5);
    if (row >= n) return;
    int lane = threadIdx.x & 31;

    int e = __ldg(&cnt[row]);
    if (e > ELL_W) e = ELL_W;
    const int2* __restrict__ pairs = ell + (size_t)row * ELL_W;
    const float4* __restrict__ d4 = reinterpret_cast<const float4*>(dense);

    float4 acc = make_float4(0.f, 0.f, 0.f, 0.f);

    int i = 0;
    for (; i + 8 <= e; i += 8) {
        int2 p[8];
#pragma unroll
        for (int k = 0; k < 8; k++) p[k] = __ldg(&pairs[i + k]);
        float4 x[8];
#pragma unroll
        for (int k = 0; k < 8; k++)
            x[k] = __ldg(&d4[(size_t)p[k].x * OUT_CH4 + lane]);
#pragma unroll
        for (int k = 0; k < 8; k++) {
            float v = __int_as_float(p[k].y);
            acc.x += v * x[k].x; acc.y += v * x[k].y;
            acc.z += v * x[k].z; acc.w += v * x[k].w;
        }
    }
    for (; i < e; i++) {
        int2 p = __ldg(&pairs[i]);
        float v = __int_as_float(p.y);
        float4 x = __ldg(&d4[(size_t)p.x * OUT_CH4 + lane]);
        acc.x += v * x.x; acc.y += v * x.y; acc.z += v * x.z; acc.w += v * x.w;
    }

    __half2 h0 = __floats2half2_rn(acc.x, acc.y);
    __half2 h1 = __floats2half2_rn(acc.z, acc.w);
    uint2 o;
    o.x = *reinterpret_cast<unsigned*>(&h0);
    o.y = *reinterpret_cast<unsigned*>(&h1);
    out[(size_t)row * OUT_CH4 + lane] = o;
}

// ---------------- graph SpMM: 2 rows/warp, 16 lanes/row, fp16 gathers ----
// Each 16-lane group owns one row; lane owns 8 consecutive fp16 columns
// (one uint4 = 16B per gather). Halves gather-LDG issue count vs 1 row/warp.
// SH: store fp16 (uint4) vs fp32 (2x float4). Accumulation fp32.
template <bool SH, bool RELU>
__global__ void __launch_bounds__(256)
spmm_ell_h16_kernel(const int* __restrict__ cnt,
                    const int2* __restrict__ ell,
                    const uint4* __restrict__ dense,   // fp16 [*, 16 uint4]
                    void* __restrict__ out,
                    int n) {
    int row = blockIdx.x * (blockDim.x >> 4) + (threadIdx.x >> 4);
    if (row >= n) return;
    int lane = threadIdx.x & 15;

    int e = __ldg(&cnt[row]);
    if (e > ELL_W) e = ELL_W;
    const int2* __restrict__ pairs = ell + (size_t)row * ELL_W;
    const int4* __restrict__ pairs4 = reinterpret_cast<const int4*>(pairs);

    float acc[8];
#pragma unroll
    for (int j = 0; j < 8; j++) acc[j] = 0.f;

    int i = 0;
    for (; i + 8 <= e; i += 8) {
        int4 q[4];
#pragma unroll
        for (int k = 0; k < 4; k++) q[k] = __ldg(&pairs4[(i >> 1) + k]);
        uint4 u[8];
#pragma unroll
        for (int k = 0; k < 4; k++) {
            u[2*k]   = __ldg(&dense[(size_t)q[k].x * OUT_CHU4 + lane]);
            u[2*k+1] = __ldg(&dense[(size_t)q[k].z * OUT_CHU4 + lane]);
        }
#pragma unroll
        for (int k = 0; k < 8; k++) {
            float v = __int_as_float(k & 1 ? q[k >> 1].w : q[k >> 1].y);
            const __half2* h = reinterpret_cast<const __half2*>(&u[k]);
#pragma unroll
            for (int j = 0; j < 4; j++) {
                float2 f = __half22float2(h[j]);
                acc[2*j]   += v * f.x;
                acc[2*j+1] += v * f.y;
            }
        }
    }
    for (; i < e; i++) {
        int2 p = __ldg(&pairs[i]);
        float v = __int_as_float(p.y);
        uint4 u = __ldg(&dense[(size_t)p.x * OUT_CHU4 + lane]);
        const __half2* h = reinterpret_cast<const __half2*>(&u);
#pragma unroll
        for (int j = 0; j < 4; j++) {
            float2 f = __half22float2(h[j]);
            acc[2*j]   += v * f.x;
            acc[2*j+1] += v * f.y;
        }
    }

    if (RELU) {
#pragma unroll
        for (int j = 0; j < 8; j++) acc[j] = acc[j] > 0.f ? acc[j] : 0.f;
    }

    if (SH) {
        uint4 o;
        __half2 h0 = __floats2half2_rn(acc[0], acc[1]);
        __half2 h1 = __floats2half2_rn(acc[2], acc[3]);
        __half2 h2 = __floats2half2_rn(acc[4], acc[5]);
        __half2 h3 = __floats2half2_rn(acc[6], acc[7]);
        o.x = *reinterpret_cast<unsigned*>(&h0);
        o.y = *reinterpret_cast<unsigned*>(&h1);
        o.z = *reinterpret_cast<unsigned*>(&h2);
        o.w = *reinterpret_cast<unsigned*>(&h3);
        reinterpret_cast<uint4*>(out)[(size_t)row * OUT_CHU4 + lane] = o;
    } else {
        float4* o4 = reinterpret_cast<float4*>(out);
        o4[(size_t)row * OUT_CH4 + lane * 2 + 0] =
            make_float4(acc[0], acc[1], acc[2], acc[3]);
        o4[(size_t)row * OUT_CH4 + lane * 2 + 1] =
            make_float4(acc[4], acc[5], acc[6], acc[7]);
    }
}

// ---------------- host-side orchestration ----------------
extern "C" void kernel_launch(void* const* d_in, const int* in_sizes, int n_in,
                              void* d_out, int out_size) {
    // Inputs: phi_indices, phi_values, phi_inverse_indices, phi_inverse_values,
    // feature_indices, feature_values, weight_matrix, diagonal_weight_filter, dropout
    const int*   phi_idx   = (const int*)d_in[0];
    const float* phi_vals  = (const float*)d_in[1];
    const int*   phii_idx  = (const int*)d_in[2];
    const float* phii_vals = (const float*)d_in[3];
    const int*   feat_idx  = (const int*)d_in[4];
    const float* feat_vals = (const float*)d_in[5];
    const float* weight    = (const float*)d_in[6];
    const float* theta     = (const float*)d_in[7];

    int nnz_phi  = in_sizes[1];
    int nnz_phii = in_sizes[3];
    int nnz_feat = in_sizes[5];
    int n_nodes  = in_sizes[7];
    (void)n_in; (void)out_size;

    float* out = (float*)d_out;
    uint2 *filtered_h, *tmp_h;
    int (*cnt)[MAX_N];
    int2 (*ell)[MAX_N * ELL_W];
    cudaGetSymbolAddress((void**)&filtered_h, g_filtered_h);
    cudaGetSymbolAddress((void**)&tmp_h, g_tmp_h);
    cudaGetSymbolAddress((void**)&cnt, g_cnt);
    cudaGetSymbolAddress((void**)&ell, g_ell);

    const int T = 256;

    // 1) Zero the three count arrays.
    cudaMemsetAsync(cnt, 0, sizeof(int) * 3 * MAX_N);

    // 2) Fused single-pass ELL build for all three matrices.
    int nnz_max = nnz_feat;
    if (nnz_phii > nnz_max) nnz_max = nnz_phii;
    if (nnz_phi  > nnz_max) nnz_max = nnz_phi;
    {
        int blocks = (nnz_max + T - 1) / T;
        build_ell_kernel<<<blocks, T>>>(feat_idx, feat_vals, nnz_feat,
                                        phii_idx, phii_vals, nnz_phii,
                                        phi_idx, phi_vals, nnz_phi,
                                        theta,
                                        cnt[0], cnt[1], cnt[2],
                                        ell[0], ell[1], ell[2]);
    }

    // 3) filtered(fp16) = feature @ W(fp32): 1 warp/row (R10 config)
    {
        int blocks = (n_nodes + (T / 32) - 1) / (T / 32);
        spmm_ell_f32_kernel<<<blocks, T>>>(cnt[0], ell[0], weight,
                                           filtered_h, n_nodes);
    }

    // 4) tmp(fp16) = phi_inv @ filtered(fp16): 2 rows/warp
    {
        int blocks = (n_nodes + (T / 16) - 1) / (T / 16);
        spmm_ell_h16_kernel<true, false><<<blocks, T>>>(
            cnt[1], ell[1], (const uint4*)filtered_h, tmp_h, n_nodes);
    }
    // 5) out(fp32) = relu( (phi*diag(theta)) @ tmp(fp16) ): 2 rows/warp
    {
        int blocks = (n_nodes + (T / 16) - 1) / (T / 16);
        spmm_ell_h16_kernel<false, true><<<blocks, T>>>(
            cnt[2], ell[2], (const uint4*)tmp_h, out, n_nodes);
    }
}